// round 3
// baseline (speedup 1.0000x reference)
#include <cuda_runtime.h>
#include <cstdint>

#define GRIDB 256
#define NTHR  256
#define Bsz   128
#define Tlen  512
#define Vocab 512
#define Emb   512
#define Hid   1024
#define G4    4096

// ---------------- device scratch (static; no runtime allocation) ----------------
__device__ float g_X[Bsz * Emb];
__device__ float g_H0[Bsz * Hid];
__device__ float g_C0[Bsz * Hid];
__device__ float g_H1[Bsz * Hid];
__device__ float g_C1[Bsz * Hid];
__device__ float g_part[4 * Bsz * G4];       // layer GEMM K-chunk partials
__device__ float g_lpart[8 * Bsz * Vocab];   // logits K-chunk partials
__device__ float g_bias0[G4];
__device__ float g_bias1[G4];
__device__ unsigned char g_dec[Tlen * Bsz];

// ---------------- software grid barrier (generation-continued) ----------------
__device__ unsigned long long g_cnt;                 // total arrivals ever
__device__ volatile unsigned long long g_gen;        // completed generations ever

__device__ __forceinline__ void grid_sync(unsigned long long& lgen) {
    __threadfence();
    __syncthreads();
    if (threadIdx.x == 0) {
        lgen += 1ULL;
        unsigned long long a = atomicAdd(&g_cnt, 1ULL) + 1ULL;
        if (a == lgen * (unsigned long long)GRIDB) {
            g_gen = lgen;                            // release
            __threadfence();
        } else {
            while (g_gen < lgen) { __nanosleep(32); }
            __threadfence();
        }
    }
    __syncthreads();
}

__device__ __forceinline__ unsigned rotl32(unsigned x, int d) {
    return (x << d) | (x >> (32 - d));
}

__device__ __forceinline__ float sigm(float x) { return 1.0f / (1.0f + expf(-x)); }

// ---------------- tiled fp32 GEMM over a virtual concatenated K ----------------
// Output tile: 128 x BN at column n0, rows = all 128 batch rows.
// Virtual K is split into two segments (A0/W0 for k-tiles [0,segTiles0), A1/W1 after).
// Processes k-tiles [ktBegin, ktEnd), each k-tile = 16 k values.
// A: [128, lda] row-major (k contiguous). W: [N, ldw] row-major (k contiguous).
// Writes fp32 partial tile to Cp (row stride ldc).
template <int BN, int RM, int RN>
__device__ __forceinline__ void gemm_tile(
    const float* __restrict__ A0, int lda0, const float* __restrict__ W0, int ldw0, int segTiles0,
    const float* __restrict__ A1, int lda1, const float* __restrict__ W1, int ldw1,
    int ktBegin, int ktEnd, int n0,
    float* __restrict__ Cp, int ldc,
    float* __restrict__ sA, float* __restrict__ sW)
{
    const int tid = threadIdx.x;
    constexpr int CG = BN / RN;             // column groups
    const int tx = tid % CG, ty = tid / CG;
    const int row0 = ty * RM, col0 = tx * RN;
    const bool hasW = (BN * 4 >= NTHR) || (tid < BN * 4);

    float4 ra[2];
    float4 rw;

    auto ldg = [&](int kt) {
        const float* A; int lda; const float* W; int ldw; int kl;
        if (kt < segTiles0) { A = A0; lda = lda0; W = W0; ldw = ldw0; kl = kt * 16; }
        else                { A = A1; lda = lda1; W = W1; ldw = ldw1; kl = (kt - segTiles0) * 16; }
#pragma unroll
        for (int l = 0; l < 2; l++) {
            int s = tid + l * NTHR;
            int r = s >> 2, q = s & 3;
            ra[l] = *(const float4*)(A + (size_t)r * lda + kl + q * 4);
        }
        if (hasW) {
            int r = tid >> 2, q = tid & 3;
            rw = *(const float4*)(W + (size_t)(n0 + r) * ldw + kl + q * 4);
        }
    };
    auto sts = [&]() {
#pragma unroll
        for (int l = 0; l < 2; l++) {
            int s = tid + l * NTHR;
            int r = s >> 2, q = s & 3;
            sA[(q * 4 + 0) * 128 + r] = ra[l].x;
            sA[(q * 4 + 1) * 128 + r] = ra[l].y;
            sA[(q * 4 + 2) * 128 + r] = ra[l].z;
            sA[(q * 4 + 3) * 128 + r] = ra[l].w;
        }
        if (hasW) {
            int r = tid >> 2, q = tid & 3;
            sW[(q * 4 + 0) * BN + r] = rw.x;
            sW[(q * 4 + 1) * BN + r] = rw.y;
            sW[(q * 4 + 2) * BN + r] = rw.z;
            sW[(q * 4 + 3) * BN + r] = rw.w;
        }
    };

    float acc[RM][RN];
#pragma unroll
    for (int i = 0; i < RM; i++)
#pragma unroll
        for (int j = 0; j < RN; j++) acc[i][j] = 0.f;

    ldg(ktBegin);
    sts();
    __syncthreads();

    for (int kt = ktBegin; kt < ktEnd; kt++) {
        if (kt + 1 < ktEnd) ldg(kt + 1);
#pragma unroll
        for (int k = 0; k < 16; k++) {
            float a[RM];
#pragma unroll
            for (int i = 0; i < RM; i += 4) {
                float4 av = *(const float4*)&sA[k * 128 + row0 + i];
                a[i] = av.x; a[i + 1] = av.y; a[i + 2] = av.z; a[i + 3] = av.w;
            }
            float4 wv = *(const float4*)&sW[k * BN + col0];
            float w[4] = { wv.x, wv.y, wv.z, wv.w };
#pragma unroll
            for (int i = 0; i < RM; i++)
#pragma unroll
                for (int j = 0; j < RN; j++)
                    acc[i][j] = fmaf(a[i], w[j], acc[i][j]);
        }
        __syncthreads();
        if (kt + 1 < ktEnd) { sts(); __syncthreads(); }
    }

#pragma unroll
    for (int i = 0; i < RM; i++) {
        float* crow = Cp + (size_t)(row0 + i) * ldc + n0 + col0;
        *(float4*)crow = make_float4(acc[i][0], acc[i][1], acc[i][2], acc[i][3]);
    }
}

// ---------------- LSTM gate nonlinearity (sums 4 K-chunk partials) ----------------
__device__ __forceinline__ void gate_phase(const float* __restrict__ bias,
                                           float* __restrict__ h, float* __restrict__ c,
                                           int blk, int tid)
{
    int base = blk * 512;   // 131072 elems / 256 blocks
    for (int e = tid; e < 512; e += NTHR) {
        int idx = base + e;
        int b = idx >> 10, j = idx & 1023;
        float gi = bias[j], gf = bias[1024 + j], gg = bias[2048 + j], go = bias[3072 + j];
        const float* pb = g_part + (size_t)b * G4;
#pragma unroll
        for (int ch = 0; ch < 4; ch++) {
            const float* q = pb + (size_t)ch * Bsz * G4;
            gi += q[j]; gf += q[1024 + j]; gg += q[2048 + j]; go += q[3072 + j];
        }
        float cc = sigm(gf) * c[idx] + sigm(gi) * tanhf(gg);
        c[idx] = cc;
        h[idx] = sigm(go) * tanhf(cc);
    }
}

// ---------------- params ----------------
struct Params {
    const int*   seq;
    const float* teacher_p;
    const float* embeds;
    const float* W_ih0; const float* W_hh0; const float* b_ih0; const float* b_hh0;
    const float* W_ih1; const float* W_hh1; const float* b_ih1; const float* b_hh1;
    const float* fc_w;  const float* fc_b;
    float* out;
};

// ---------------- the persistent kernel ----------------
__global__ void __launch_bounds__(NTHR, 2) lstm_persist(Params P)
{
    __shared__ float sA[16 * 128];
    __shared__ float sW[16 * 64];
    __shared__ float red_v[NTHR];
    __shared__ int   red_i[NTHR];
    __shared__ int   s_tok;

    const int tid = threadIdx.x;
    const int blk = blockIdx.x;
    unsigned long long lgen = g_gen;   // generation continuation across launches

    // ================= setup =================
    {   // zero states: 131072 elems per array, 512 per block
        int base = blk * 512;
        for (int e = tid; e < 512; e += NTHR) {
            g_H0[base + e] = 0.f; g_C0[base + e] = 0.f;
            g_H1[base + e] = 0.f; g_C1[base + e] = 0.f;
        }
    }
    if (blk >= 128 && blk < 160) {   // combined biases
        int i = (blk - 128) * NTHR + tid;   // 0..8191
        if (i < 4096) g_bias0[i] = P.b_ih0[i] + P.b_hh0[i];
        else { int j = i - 4096; g_bias1[j] = P.b_ih1[j] + P.b_hh1[j]; }
    }
    if (blk < 128) {
        // threefry-2x32, PARTITIONABLE scheme (modern JAX default):
        // bits[i] = o0 ^ o1 where (o0,o1) = threefry2x32(key=(0,1), (hi32(i)=0, lo32(i)=i))
        int j = blk * NTHR + tid;   // flat element index 0..32767 (covers T*B via 2 elems/thread? no: 128*256=32768; need 65536)
        const unsigned ks0 = 0u, ks1 = 1u, ks2 = 0u ^ 1u ^ 0x1BD11BDAu;
#pragma unroll
        for (int half = 0; half < 2; half++) {
            unsigned idx = (unsigned)j + (unsigned)half * 32768u;
            unsigned x0 = 0u;        // hi32 of the uint64 count
            unsigned x1 = idx;       // lo32 of the uint64 count
            x0 += ks0; x1 += ks1;
#define R4(a,b,c,d) \
            x0 += x1; x1 = rotl32(x1,a); x1 ^= x0; \
            x0 += x1; x1 = rotl32(x1,b); x1 ^= x0; \
            x0 += x1; x1 = rotl32(x1,c); x1 ^= x0; \
            x0 += x1; x1 = rotl32(x1,d); x1 ^= x0;
            R4(13,15,26,6);   x0 += ks1; x1 += ks2 + 1u;
            R4(17,29,16,24);  x0 += ks2; x1 += ks0 + 2u;
            R4(13,15,26,6);   x0 += ks0; x1 += ks1 + 3u;
            R4(17,29,16,24);  x0 += ks1; x1 += ks2 + 4u;
            R4(13,15,26,6);   x0 += ks2; x1 += ks0 + 5u;
#undef R4
            unsigned bits = x0 ^ x1;
            float p = *P.teacher_p;
            float u = __uint_as_float((bits >> 9) | 0x3f800000u) - 1.0f;
            g_dec[idx] = (u < p) ? 1 : 0;
        }

        // embed for t = 0 (always teacher-forced)
        int b = blk;
        int tok = P.seq[b * Tlen];
        const float4* src = (const float4*)(P.embeds + (size_t)tok * Emb);
        float4* dst = (float4*)(g_X + (size_t)b * Emb);
        if (tid < 128)
            dst[tid] = (tok == 0) ? make_float4(0.f, 0.f, 0.f, 0.f) : src[tid];
    }
    grid_sync(lgen);

    // ================= time loop =================
    for (int t = 0; t < Tlen; t++) {
        // ---- layer 0: g = X @ W_ih0^T + H0 @ W_hh0^T (virtual K = 512|1024 = 96 k-tiles)
        {
            int tile = blk & 63, chunk = blk >> 6;   // 64 tiles x 4 chunks = 256 units
            gemm_tile<64, 8, 4>(g_X, Emb, P.W_ih0, Emb, 32,
                                g_H0, Hid, P.W_hh0, Hid,
                                chunk * 24, chunk * 24 + 24, tile * 64,
                                g_part + (size_t)chunk * Bsz * G4, G4, sA, sW);
        }
        grid_sync(lgen);
        gate_phase(g_bias0, g_H0, g_C0, blk, tid);
        grid_sync(lgen);

        // ---- layer 1: g = H0 @ W_ih1^T + H1 @ W_hh1^T (virtual K = 1024|1024 = 128 k-tiles)
        {
            int tile = blk & 63, chunk = blk >> 6;
            gemm_tile<64, 8, 4>(g_H0, Hid, P.W_ih1, Hid, 64,
                                g_H1, Hid, P.W_hh1, Hid,
                                chunk * 32, chunk * 32 + 32, tile * 64,
                                g_part + (size_t)chunk * Bsz * G4, G4, sA, sW);
        }
        grid_sync(lgen);
        gate_phase(g_bias1, g_H1, g_C1, blk, tid);
        grid_sync(lgen);

        // ---- logits: H1 @ fc_w^T (K = 1024 = 64 k-tiles; 16 N-tiles x 8 chunks = 128 units)
        if (blk < 128) {
            int tile = blk & 15, chunk = blk >> 4;
            gemm_tile<32, 4, 4>(g_H1, Hid, P.fc_w, Hid, 64,
                                g_H1, Hid, P.fc_w, Hid,   // seg1 never reached
                                chunk * 8, chunk * 8 + 8, tile * 32,
                                g_lpart + (size_t)chunk * Bsz * Vocab, Vocab, sA, sW);
        }
        grid_sync(lgen);

        // ---- epilogue: sum 8 partials + bias, write out, argmax, next-token embed
        if (blk < 128) {
            int b = blk;
            float* orow = P.out + ((size_t)b * Tlen + t) * Vocab;
            float bv = -3.402823e38f; int bi = 0;
            for (int n = tid; n < Vocab; n += NTHR) {
                float v = P.fc_b[n];
#pragma unroll
                for (int ch = 0; ch < 8; ch++)
                    v += g_lpart[(size_t)ch * Bsz * Vocab + b * Vocab + n];
                orow[n] = v;
                if (v > bv) { bv = v; bi = n; }   // ascending n: strict > keeps first max
            }
            red_v[tid] = bv; red_i[tid] = bi;
            __syncthreads();
            for (int s = NTHR / 2; s > 0; s >>= 1) {
                if (tid < s) {
                    float v2 = red_v[tid + s]; int i2 = red_i[tid + s];
                    if (v2 > red_v[tid] || (v2 == red_v[tid] && i2 < red_i[tid])) {
                        red_v[tid] = v2; red_i[tid] = i2;
                    }
                }
                __syncthreads();
            }
            if (t + 1 < Tlen) {
                if (tid == 0) {
                    bool teacher = g_dec[(t + 1) * Bsz + b] != 0;
                    s_tok = teacher ? P.seq[b * Tlen + (t + 1)] : red_i[0];
                }
                __syncthreads();
                int tok = s_tok;
                const float4* src = (const float4*)(P.embeds + (size_t)tok * Emb);
                float4* dst = (float4*)(g_X + (size_t)b * Emb);
                if (tid < 128)
                    dst[tid] = (tok == 0) ? make_float4(0.f, 0.f, 0.f, 0.f) : src[tid];
            }
        }
        grid_sync(lgen);
    }
}

// ---------------- host launch: ONE kernel node, fully graph-capturable ----------------
extern "C" void kernel_launch(void* const* d_in, const int* in_sizes, int n_in,
                              void* d_out, int out_size)
{
    Params P;
    P.seq       = (const int*)d_in[0];
    // d_in[1] = seq_lens (unused by the reference computation)
    P.teacher_p = (const float*)d_in[2];
    P.embeds    = (const float*)d_in[3];
    P.W_ih0     = (const float*)d_in[4];
    P.W_hh0     = (const float*)d_in[5];
    P.b_ih0     = (const float*)d_in[6];
    P.b_hh0     = (const float*)d_in[7];
    P.W_ih1     = (const float*)d_in[8];
    P.W_hh1     = (const float*)d_in[9];
    P.b_ih1     = (const float*)d_in[10];
    P.b_hh1     = (const float*)d_in[11];
    P.fc_w      = (const float*)d_in[12];
    P.fc_b      = (const float*)d_in[13];
    P.out       = (float*)d_out;

    lstm_persist<<<GRIDB, NTHR>>>(P);
}

// round 4
// speedup vs baseline: 1.0230x; 1.0230x over previous
#include <cuda_runtime.h>
#include <cstdint>

#define GRIDB 256
#define NTHR  256
#define Bsz   128
#define Tlen  512
#define Vocab 512
#define Emb   512
#define Hid   1024
#define G4    4096

// ---------------- device scratch (static; no runtime allocation) ----------------
__device__ float g_X[Bsz * Emb];
__device__ float g_H0[Bsz * Hid];
__device__ float g_C0[Bsz * Hid];
__device__ float g_H1[Bsz * Hid];
__device__ float g_C1[Bsz * Hid];
__device__ float g_part[8 * Bsz * G4];        // layer GEMM K-chunk partials (8 chunks)
__device__ float g_lpart[16 * Bsz * Vocab];   // logits K-chunk partials (16 chunks)
__device__ float g_bias0[G4];
__device__ float g_bias1[G4];
__device__ unsigned char g_dec[Tlen * Bsz];

// ---------------- software grid barrier (generation-continued) ----------------
__device__ unsigned long long g_cnt;
__device__ volatile unsigned long long g_gen;

__device__ __forceinline__ void grid_sync(unsigned long long& lgen) {
    __threadfence();
    __syncthreads();
    if (threadIdx.x == 0) {
        lgen += 1ULL;
        unsigned long long a = atomicAdd(&g_cnt, 1ULL) + 1ULL;
        if (a == lgen * (unsigned long long)GRIDB) {
            g_gen = lgen;
            __threadfence();
        } else {
            while (g_gen < lgen) { __nanosleep(32); }
            __threadfence();
        }
    }
    __syncthreads();
}

__device__ __forceinline__ unsigned rotl32(unsigned x, int d) {
    return (x << d) | (x >> (32 - d));
}

__device__ __forceinline__ float sigm(float x) { return 1.0f / (1.0f + expf(-x)); }

// ---------------- packed f32x2 helpers ----------------
#define PK2(d, s) asm("mov.b64 %0, {%1, %1};" : "=l"(d) : "r"(__float_as_uint(s)))
#define FMA2(acc, a, b) \
    asm("fma.rn.f32x2 %0, %1, %2, %3;" : "=l"(acc) : "l"(a), "l"(b), "l"(acc))

// ---------------- packed-f32x2 tiled GEMM over a virtual concatenated K ----------------
// Output tile: 128 x BN at column n0 (all 128 batch rows).
// Virtual K split into two segments; processes k-tiles [ktBegin, ktEnd), k-tile = 16 k.
// A: [128, lda] row-major; W: [N, ldw] row-major (k contiguous). Writes fp32 tile to Cp.
template <int BN, int RM, int RN>
__device__ __forceinline__ void gemm2(
    const float* __restrict__ A0, int lda0, const float* __restrict__ W0, int ldw0, int segTiles0,
    const float* __restrict__ A1, int lda1, const float* __restrict__ W1, int ldw1,
    int ktBegin, int ktEnd, int n0,
    float* __restrict__ Cp, int ldc,
    float* __restrict__ sA, float* __restrict__ sW)
{
    const int tid = threadIdx.x;
    constexpr int CG  = BN / RN;               // column groups
    constexpr int RNP = RN / 2;                // packed accumulator pairs per row
    const int tx = tid % CG, ty = tid / CG;
    const int row0 = ty * RM, col0 = tx * RN;

    constexpr int WV4 = 4 * BN;                // total W float4s per k-tile (16*BN/4)
    constexpr int WSLOT = (WV4 + NTHR - 1) / NTHR;

    float4 ra[2];
    float4 rw[WSLOT];

    auto ldg = [&](int kt) {
        const float* A; int lda; const float* W; int ldw; int kl;
        if (kt < segTiles0) { A = A0; lda = lda0; W = W0; ldw = ldw0; kl = kt * 16; }
        else                { A = A1; lda = lda1; W = W1; ldw = ldw1; kl = (kt - segTiles0) * 16; }
#pragma unroll
        for (int l = 0; l < 2; l++) {
            int s = tid + l * NTHR;
            int r = s >> 2, q = s & 3;
            ra[l] = *(const float4*)(A + (size_t)r * lda + kl + q * 4);
        }
#pragma unroll
        for (int l = 0; l < WSLOT; l++) {
            int s = tid + l * NTHR;
            if (WV4 >= NTHR || s < WV4) {
                int wn = s >> 2, q = s & 3;
                rw[l] = *(const float4*)(W + (size_t)(n0 + wn) * ldw + kl + q * 4);
            }
        }
    };
    auto sts = [&]() {
#pragma unroll
        for (int l = 0; l < 2; l++) {
            int s = tid + l * NTHR;
            int r = s >> 2, q = s & 3;
            sA[(q * 4 + 0) * 128 + r] = ra[l].x;
            sA[(q * 4 + 1) * 128 + r] = ra[l].y;
            sA[(q * 4 + 2) * 128 + r] = ra[l].z;
            sA[(q * 4 + 3) * 128 + r] = ra[l].w;
        }
#pragma unroll
        for (int l = 0; l < WSLOT; l++) {
            int s = tid + l * NTHR;
            if (WV4 >= NTHR || s < WV4) {
                int wn = s >> 2, q = s & 3;
                sW[(q * 4 + 0) * BN + wn] = rw[l].x;
                sW[(q * 4 + 1) * BN + wn] = rw[l].y;
                sW[(q * 4 + 2) * BN + wn] = rw[l].z;
                sW[(q * 4 + 3) * BN + wn] = rw[l].w;
            }
        }
    };

    unsigned long long acc2[RM][RNP];
#pragma unroll
    for (int i = 0; i < RM; i++)
#pragma unroll
        for (int j = 0; j < RNP; j++) acc2[i][j] = 0ULL;

    ldg(ktBegin);
    sts();
    __syncthreads();

    for (int kt = ktBegin; kt < ktEnd; kt++) {
        if (kt + 1 < ktEnd) ldg(kt + 1);
#pragma unroll
        for (int k = 0; k < 16; k++) {
            float a[RM];
#pragma unroll
            for (int i = 0; i < RM; i += 4) {
                float4 av = *(const float4*)&sA[k * 128 + row0 + i];
                a[i] = av.x; a[i + 1] = av.y; a[i + 2] = av.z; a[i + 3] = av.w;
            }
            unsigned long long w2[RNP];
            const ulonglong2* wp = (const ulonglong2*)&sW[k * BN + col0];
#pragma unroll
            for (int j = 0; j < RNP; j += 2) {
                ulonglong2 wv = wp[j >> 1];
                w2[j] = wv.x; w2[j + 1] = wv.y;
            }
#pragma unroll
            for (int i = 0; i < RM; i++) {
                unsigned long long a2;
                PK2(a2, a[i]);
#pragma unroll
                for (int j = 0; j < RNP; j++)
                    FMA2(acc2[i][j], a2, w2[j]);
            }
        }
        __syncthreads();
        if (kt + 1 < ktEnd) { sts(); __syncthreads(); }
    }

#pragma unroll
    for (int i = 0; i < RM; i++) {
        ulonglong2* crow = (ulonglong2*)(Cp + (size_t)(row0 + i) * ldc + n0 + col0);
#pragma unroll
        for (int j = 0; j < RNP; j += 2)
            crow[j >> 1] = make_ulonglong2(acc2[i][j], acc2[i][j + 1]);
    }
}

// ---------------- LSTM gate nonlinearity (sums 8 K-chunk partials) ----------------
__device__ __forceinline__ void gate_phase(const float* __restrict__ bias,
                                           float* __restrict__ h, float* __restrict__ c,
                                           int blk, int tid)
{
    int base = blk * 512;   // 131072 elems / 256 blocks
    for (int e = tid; e < 512; e += NTHR) {
        int idx = base + e;
        int b = idx >> 10, j = idx & 1023;
        float gi = bias[j], gf = bias[1024 + j], gg = bias[2048 + j], go = bias[3072 + j];
        const float* pb = g_part + (size_t)b * G4;
#pragma unroll
        for (int ch = 0; ch < 8; ch++) {
            const float* q = pb + (size_t)ch * Bsz * G4;
            gi += q[j]; gf += q[1024 + j]; gg += q[2048 + j]; go += q[3072 + j];
        }
        float cc = sigm(gf) * c[idx] + sigm(gi) * tanhf(gg);
        c[idx] = cc;
        h[idx] = sigm(go) * tanhf(cc);
    }
}

// ---------------- params ----------------
struct Params {
    const int*   seq;
    const float* teacher_p;
    const float* embeds;
    const float* W_ih0; const float* W_hh0; const float* b_ih0; const float* b_hh0;
    const float* W_ih1; const float* W_hh1; const float* b_ih1; const float* b_hh1;
    const float* fc_w;  const float* fc_b;
    float* out;
};

// ---------------- the persistent kernel ----------------
__global__ void __launch_bounds__(NTHR, 2) lstm_persist(Params P)
{
    __shared__ float sA[16 * 128];
    __shared__ float sW[16 * 128];
    __shared__ float red_v[NTHR];
    __shared__ int   red_i[NTHR];
    __shared__ int   s_tok;

    const int tid = threadIdx.x;
    const int blk = blockIdx.x;
    unsigned long long lgen = g_gen;   // generation continuation across graph replays

    // ================= setup =================
    {
        int base = blk * 512;
        for (int e = tid; e < 512; e += NTHR) {
            g_H0[base + e] = 0.f; g_C0[base + e] = 0.f;
            g_H1[base + e] = 0.f; g_C1[base + e] = 0.f;
        }
    }
    if (blk >= 128 && blk < 160) {
        int i = (blk - 128) * NTHR + tid;
        if (i < 4096) g_bias0[i] = P.b_ih0[i] + P.b_hh0[i];
        else { int j = i - 4096; g_bias1[j] = P.b_ih1[j] + P.b_hh1[j]; }
    }
    if (blk < 128) {
        // threefry-2x32, partitionable scheme: bits[i] = o0 ^ o1,
        // (o0,o1) = threefry2x32(key=(0,1), (hi32(i)=0, lo32(i)=i))
        int j = blk * NTHR + tid;
        const unsigned ks0 = 0u, ks1 = 1u, ks2 = 0u ^ 1u ^ 0x1BD11BDAu;
#pragma unroll
        for (int half = 0; half < 2; half++) {
            unsigned idx = (unsigned)j + (unsigned)half * 32768u;
            unsigned x0 = 0u;
            unsigned x1 = idx;
            x0 += ks0; x1 += ks1;
#define R4(a,b,c,d) \
            x0 += x1; x1 = rotl32(x1,a); x1 ^= x0; \
            x0 += x1; x1 = rotl32(x1,b); x1 ^= x0; \
            x0 += x1; x1 = rotl32(x1,c); x1 ^= x0; \
            x0 += x1; x1 = rotl32(x1,d); x1 ^= x0;
            R4(13,15,26,6);   x0 += ks1; x1 += ks2 + 1u;
            R4(17,29,16,24);  x0 += ks2; x1 += ks0 + 2u;
            R4(13,15,26,6);   x0 += ks0; x1 += ks1 + 3u;
            R4(17,29,16,24);  x0 += ks1; x1 += ks2 + 4u;
            R4(13,15,26,6);   x0 += ks2; x1 += ks0 + 5u;
#undef R4
            unsigned bits = x0 ^ x1;
            float p = *P.teacher_p;
            float u = __uint_as_float((bits >> 9) | 0x3f800000u) - 1.0f;
            g_dec[idx] = (u < p) ? 1 : 0;
        }

        // embed for t = 0 (always teacher-forced)
        int b = blk;
        int tok = P.seq[b * Tlen];
        const float4* src = (const float4*)(P.embeds + (size_t)tok * Emb);
        float4* dst = (float4*)(g_X + (size_t)b * Emb);
        if (tid < 128)
            dst[tid] = (tok == 0) ? make_float4(0.f, 0.f, 0.f, 0.f) : src[tid];
    }
    grid_sync(lgen);

    // ================= time loop =================
    for (int t = 0; t < Tlen; t++) {
        // ---- layer 0: g = X @ W_ih0^T + H0 @ W_hh0^T (virtual K = 512|1024, 96 k-tiles)
        {
            int tile = blk & 31, chunk = blk >> 5;   // 32 tiles(128) x 8 chunks(12 k-tiles)
            gemm2<128, 8, 8>(g_X, Emb, P.W_ih0, Emb, 32,
                             g_H0, Hid, P.W_hh0, Hid,
                             chunk * 12, chunk * 12 + 12, tile * 128,
                             g_part + (size_t)chunk * Bsz * G4, G4, sA, sW);
        }
        grid_sync(lgen);
        gate_phase(g_bias0, g_H0, g_C0, blk, tid);
        grid_sync(lgen);

        // ---- layer 1: g = H0 @ W_ih1^T + H1 @ W_hh1^T (virtual K = 1024|1024, 128 k-tiles)
        {
            int tile = blk & 31, chunk = blk >> 5;   // 32 tiles x 8 chunks(16 k-tiles)
            gemm2<128, 8, 8>(g_H0, Hid, P.W_ih1, Hid, 64,
                             g_H1, Hid, P.W_hh1, Hid,
                             chunk * 16, chunk * 16 + 16, tile * 128,
                             g_part + (size_t)chunk * Bsz * G4, G4, sA, sW);
        }
        grid_sync(lgen);
        gate_phase(g_bias1, g_H1, g_C1, blk, tid);
        grid_sync(lgen);

        // ---- logits: H1 @ fc_w^T (K = 1024 = 64 k-tiles; 16 tiles(32) x 16 chunks(4))
        {
            int tile = blk & 15, chunk = blk >> 4;
            gemm2<32, 4, 4>(g_H1, Hid, P.fc_w, Hid, 64,
                            g_H1, Hid, P.fc_w, Hid,   // seg1 never reached
                            chunk * 4, chunk * 4 + 4, tile * 32,
                            g_lpart + (size_t)chunk * Bsz * Vocab, Vocab, sA, sW);
        }
        grid_sync(lgen);

        // ---- epilogue: sum 16 partials + bias, write out, argmax, next-token embed
        if (blk < 128) {
            int b = blk;
            float* orow = P.out + ((size_t)b * Tlen + t) * Vocab;
            float bv = -3.402823e38f; int bi = 0;
            for (int n = tid; n < Vocab; n += NTHR) {
                float v = P.fc_b[n];
#pragma unroll
                for (int ch = 0; ch < 16; ch++)
                    v += g_lpart[(size_t)ch * Bsz * Vocab + b * Vocab + n];
                orow[n] = v;
                if (v > bv) { bv = v; bi = n; }
            }
            red_v[tid] = bv; red_i[tid] = bi;
            __syncthreads();
            for (int s = NTHR / 2; s > 0; s >>= 1) {
                if (tid < s) {
                    float v2 = red_v[tid + s]; int i2 = red_i[tid + s];
                    if (v2 > red_v[tid] || (v2 == red_v[tid] && i2 < red_i[tid])) {
                        red_v[tid] = v2; red_i[tid] = i2;
                    }
                }
                __syncthreads();
            }
            if (t + 1 < Tlen) {
                if (tid == 0) {
                    bool teacher = g_dec[(t + 1) * Bsz + b] != 0;
                    s_tok = teacher ? P.seq[b * Tlen + (t + 1)] : red_i[0];
                }
                __syncthreads();
                int tok = s_tok;
                const float4* src = (const float4*)(P.embeds + (size_t)tok * Emb);
                float4* dst = (float4*)(g_X + (size_t)b * Emb);
                if (tid < 128)
                    dst[tid] = (tok == 0) ? make_float4(0.f, 0.f, 0.f, 0.f) : src[tid];
            }
        }
        grid_sync(lgen);
    }
}

// ---------------- host launch: ONE kernel node, fully graph-capturable ----------------
extern "C" void kernel_launch(void* const* d_in, const int* in_sizes, int n_in,
                              void* d_out, int out_size)
{
    Params P;
    P.seq       = (const int*)d_in[0];
    // d_in[1] = seq_lens (unused by the reference computation)
    P.teacher_p = (const float*)d_in[2];
    P.embeds    = (const float*)d_in[3];
    P.W_ih0     = (const float*)d_in[4];
    P.W_hh0     = (const float*)d_in[5];
    P.b_ih0     = (const float*)d_in[6];
    P.b_hh0     = (const float*)d_in[7];
    P.W_ih1     = (const float*)d_in[8];
    P.W_hh1     = (const float*)d_in[9];
    P.b_ih1     = (const float*)d_in[10];
    P.b_hh1     = (const float*)d_in[11];
    P.fc_w      = (const float*)d_in[12];
    P.fc_b      = (const float*)d_in[13];
    P.out       = (float*)d_out;

    lstm_persist<<<GRIDB, NTHR>>>(P);
}

// round 5
// speedup vs baseline: 1.2292x; 1.2016x over previous
#include <cuda_runtime.h>
#include <cstdint>

#define GRIDB 288
#define NTHR  256
#define Bsz   128
#define Tlen  512
#define Vocab 512
#define Emb   512
#define Hid   1024
#define G4    4096

// ---------------- device scratch (static; no runtime allocation) ----------------
__device__ float g_X[Bsz * Emb];
__device__ float g_H0[Bsz * Hid];
__device__ float g_C0[Bsz * Hid];
__device__ float g_H1[Bsz * Hid];
__device__ float g_C1[Bsz * Hid];
__device__ float g_part[9 * Bsz * G4];        // layer GEMM K-chunk partials (9 chunks)
__device__ float g_lpart[18 * Bsz * Vocab];   // logits K-chunk partials (18 chunks)
__device__ float g_bias0[G4];
__device__ float g_bias1[G4];
__device__ unsigned char g_dec[Tlen * Bsz];

// ---------------- software grid barrier (generation-continued) ----------------
__device__ unsigned long long g_cnt;
__device__ volatile unsigned long long g_gen;

__device__ __forceinline__ void grid_sync(unsigned long long& lgen) {
    __threadfence();
    __syncthreads();
    if (threadIdx.x == 0) {
        lgen += 1ULL;
        unsigned long long a = atomicAdd(&g_cnt, 1ULL) + 1ULL;
        if (a == lgen * (unsigned long long)GRIDB) {
            g_gen = lgen;
            __threadfence();
        } else {
            while (g_gen < lgen) { __nanosleep(32); }
            __threadfence();
        }
    }
    __syncthreads();
}

__device__ __forceinline__ unsigned rotl32(unsigned x, int d) {
    return (x << d) | (x >> (32 - d));
}

__device__ __forceinline__ float sigm(float x) { return 1.0f / (1.0f + expf(-x)); }

// ---------------- packed f32x2 helpers ----------------
#define PK2(d, s) asm("mov.b64 %0, {%1, %1};" : "=l"(d) : "r"(__float_as_uint(s)))
#define FMA2(acc, a, b) \
    asm("fma.rn.f32x2 %0, %1, %2, %3;" : "=l"(acc) : "l"(a), "l"(b), "l"(acc))

#define LA 132                         // sA row stride (pad 4: 16B-aligned, 2-way STS max)

// ---------------- packed-f32x2 double-buffered GEMM over a virtual concatenated K ----
// Output tile: 128 x BN at column n0 (all 128 batch rows). k-tile = 16 k values.
// Thread micro-tile: RM rows x (NG groups of 4 cols): group g at col n0 + g*BN/2 + tx*4.
// A: [128, lda] row-major; W: [N, ldw] row-major (k contiguous). fp32 tile -> Cp.
template <int BN, int RM, int NG>
__device__ __forceinline__ void gemm2(
    const float* __restrict__ A0, int lda0, const float* __restrict__ W0, int ldw0, int segTiles0,
    const float* __restrict__ A1, int lda1, const float* __restrict__ W1, int ldw1,
    int ktBegin, int ktEnd, int n0,
    float* __restrict__ Cp, int ldc,
    float* __restrict__ sA, float* __restrict__ sW)
{
    constexpr int LW  = BN + 4;        // sW row stride (padded)
    constexpr int RN  = NG * 4;
    constexpr int CG  = BN / RN;       // column groups of threads
    constexpr int GOFF = BN / 2;       // second col-group offset (NG==2)
    const int tid  = threadIdx.x;
    const int tx   = tid % CG, ty = tid / CG;
    const int row0 = ty * RM;
    const int colA = tx * 4;

    constexpr int WV4   = 4 * BN;      // W float4s per k-tile
    constexpr int WSLOT = (WV4 + NTHR - 1) / NTHR;

    float4 ra[2];
    float4 rw[WSLOT];

    auto ldg = [&](int kt) {
        const float* A; int lda; const float* W; int ldw; int kl;
        if (kt < segTiles0) { A = A0; lda = lda0; W = W0; ldw = ldw0; kl = kt * 16; }
        else                { A = A1; lda = lda1; W = W1; ldw = ldw1; kl = (kt - segTiles0) * 16; }
#pragma unroll
        for (int l = 0; l < 2; l++) {
            int s = tid + l * NTHR;
            int r = s >> 2, q = s & 3;
            ra[l] = *(const float4*)(A + (size_t)r * lda + kl + q * 4);
        }
#pragma unroll
        for (int l = 0; l < WSLOT; l++) {
            int s = tid + l * NTHR;
            if (WV4 >= NTHR || s < WV4) {
                int wn = s >> 2, q = s & 3;
                rw[l] = *(const float4*)(W + (size_t)(n0 + wn) * ldw + kl + q * 4);
            }
        }
    };
    auto sts = [&](int st) {
        float* A_ = sA + st * (16 * LA);
        float* W_ = sW + st * (16 * LW);
#pragma unroll
        for (int l = 0; l < 2; l++) {
            int s = tid + l * NTHR;
            int r = s >> 2, q = s & 3;
            A_[(q * 4 + 0) * LA + r] = ra[l].x;
            A_[(q * 4 + 1) * LA + r] = ra[l].y;
            A_[(q * 4 + 2) * LA + r] = ra[l].z;
            A_[(q * 4 + 3) * LA + r] = ra[l].w;
        }
#pragma unroll
        for (int l = 0; l < WSLOT; l++) {
            int s = tid + l * NTHR;
            if (WV4 >= NTHR || s < WV4) {
                int wn = s >> 2, q = s & 3;
                W_[(q * 4 + 0) * LW + wn] = rw[l].x;
                W_[(q * 4 + 1) * LW + wn] = rw[l].y;
                W_[(q * 4 + 2) * LW + wn] = rw[l].z;
                W_[(q * 4 + 3) * LW + wn] = rw[l].w;
            }
        }
    };

    unsigned long long acc2[RM][NG * 2];
#pragma unroll
    for (int i = 0; i < RM; i++)
#pragma unroll
        for (int j = 0; j < NG * 2; j++) acc2[i][j] = 0ULL;

    ldg(ktBegin);
    sts(0);
    __syncthreads();

    for (int kt = ktBegin; kt < ktEnd; kt++) {
        if (kt + 1 < ktEnd) ldg(kt + 1);
        const int st = (kt - ktBegin) & 1;
        const float* A_ = sA + st * (16 * LA);
        const float* W_ = sW + st * (16 * LW);
#pragma unroll
        for (int k = 0; k < 16; k++) {
            float a[RM];
#pragma unroll
            for (int i = 0; i < RM; i += 4) {
                float4 av = *(const float4*)&A_[k * LA + row0 + i];
                a[i] = av.x; a[i + 1] = av.y; a[i + 2] = av.z; a[i + 3] = av.w;
            }
            unsigned long long w2[NG * 2];
            {
                ulonglong2 wv0 = *(const ulonglong2*)&W_[k * LW + colA];
                w2[0] = wv0.x; w2[1] = wv0.y;
                if (NG == 2) {
                    ulonglong2 wv1 = *(const ulonglong2*)&W_[k * LW + GOFF + colA];
                    w2[2] = wv1.x; w2[3] = wv1.y;
                }
            }
#pragma unroll
            for (int i = 0; i < RM; i++) {
                unsigned long long a2;
                PK2(a2, a[i]);
#pragma unroll
                for (int j = 0; j < NG * 2; j++)
                    FMA2(acc2[i][j], a2, w2[j]);
            }
        }
        if (kt + 1 < ktEnd) sts(st ^ 1);   // safe: all warps are past sync(kt-1)
        __syncthreads();
    }

#pragma unroll
    for (int i = 0; i < RM; i++) {
        float* crow = Cp + (size_t)(row0 + i) * ldc + n0;
        *(ulonglong2*)(crow + colA) = make_ulonglong2(acc2[i][0], acc2[i][1]);
        if (NG == 2)
            *(ulonglong2*)(crow + GOFF + colA) = make_ulonglong2(acc2[i][2], acc2[i][3]);
    }
}

// ---------------- LSTM gate nonlinearity (sums 9 K-chunk partials) ----------------
__device__ __forceinline__ void gate_phase(const float* __restrict__ bias,
                                           float* __restrict__ h, float* __restrict__ c,
                                           int gtid)
{
    for (int idx = gtid; idx < Bsz * Hid; idx += GRIDB * NTHR) {
        int b = idx >> 10, j = idx & 1023;
        float gi = bias[j], gf = bias[1024 + j], gg = bias[2048 + j], go = bias[3072 + j];
        const float* pb = g_part + (size_t)b * G4;
#pragma unroll
        for (int ch = 0; ch < 9; ch++) {
            const float* q = pb + (size_t)ch * Bsz * G4;
            gi += q[j]; gf += q[1024 + j]; gg += q[2048 + j]; go += q[3072 + j];
        }
        float cc = sigm(gf) * c[idx] + sigm(gi) * tanhf(gg);
        c[idx] = cc;
        h[idx] = sigm(go) * tanhf(cc);
    }
}

// ---------------- params ----------------
struct Params {
    const int*   seq;
    const float* teacher_p;
    const float* embeds;
    const float* W_ih0; const float* W_hh0; const float* b_ih0; const float* b_hh0;
    const float* W_ih1; const float* W_hh1; const float* b_ih1; const float* b_hh1;
    const float* fc_w;  const float* fc_b;
    float* out;
};

// ---------------- the persistent kernel ----------------
__global__ void __launch_bounds__(NTHR, 2) lstm_persist(Params P)
{
    __shared__ float sA[2 * 16 * LA];
    __shared__ float sW[2 * 16 * (128 + 4)];
    __shared__ float red_v[NTHR];
    __shared__ int   red_i[NTHR];
    __shared__ int   s_tok;

    const int tid  = threadIdx.x;
    const int blk  = blockIdx.x;
    const int gtid = blk * NTHR + tid;
    unsigned long long lgen = g_gen;   // generation continuation across graph replays

    // ================= setup =================
    for (int idx = gtid; idx < Bsz * Hid; idx += GRIDB * NTHR) {
        g_H0[idx] = 0.f; g_C0[idx] = 0.f; g_H1[idx] = 0.f; g_C1[idx] = 0.f;
    }
    if (blk >= 128 && blk < 160) {
        int i = (blk - 128) * NTHR + tid;
        if (i < 4096) g_bias0[i] = P.b_ih0[i] + P.b_hh0[i];
        else { int j = i - 4096; g_bias1[j] = P.b_ih1[j] + P.b_hh1[j]; }
    }
    if (blk < 128) {
        // threefry-2x32, partitionable scheme: bits[i] = o0 ^ o1,
        // (o0,o1) = threefry2x32(key=(0,1), (hi32(i)=0, lo32(i)=i))
        int j = blk * NTHR + tid;
        const unsigned ks0 = 0u, ks1 = 1u, ks2 = 0u ^ 1u ^ 0x1BD11BDAu;
#pragma unroll
        for (int half = 0; half < 2; half++) {
            unsigned idx = (unsigned)j + (unsigned)half * 32768u;
            unsigned x0 = 0u;
            unsigned x1 = idx;
            x0 += ks0; x1 += ks1;
#define R4(a,b,c,d) \
            x0 += x1; x1 = rotl32(x1,a); x1 ^= x0; \
            x0 += x1; x1 = rotl32(x1,b); x1 ^= x0; \
            x0 += x1; x1 = rotl32(x1,c); x1 ^= x0; \
            x0 += x1; x1 = rotl32(x1,d); x1 ^= x0;
            R4(13,15,26,6);   x0 += ks1; x1 += ks2 + 1u;
            R4(17,29,16,24);  x0 += ks2; x1 += ks0 + 2u;
            R4(13,15,26,6);   x0 += ks0; x1 += ks1 + 3u;
            R4(17,29,16,24);  x0 += ks1; x1 += ks2 + 4u;
            R4(13,15,26,6);   x0 += ks2; x1 += ks0 + 5u;
#undef R4
            unsigned bits = x0 ^ x1;
            float p = *P.teacher_p;
            float u = __uint_as_float((bits >> 9) | 0x3f800000u) - 1.0f;
            g_dec[idx] = (u < p) ? 1 : 0;
        }

        // embed for t = 0 (always teacher-forced)
        int b = blk;
        int tok = P.seq[b * Tlen];
        const float4* src = (const float4*)(P.embeds + (size_t)tok * Emb);
        float4* dst = (float4*)(g_X + (size_t)b * Emb);
        if (tid < 128)
            dst[tid] = (tok == 0) ? make_float4(0.f, 0.f, 0.f, 0.f) : src[tid];
    }
    grid_sync(lgen);

    // ================= time loop =================
    for (int t = 0; t < Tlen; t++) {
        // ---- layer 0: g = X @ W_ih0^T + H0 @ W_hh0^T (virtual K = 512|1024, 96 k-tiles)
        {
            int tile = blk % 32, chunk = blk / 32;   // 32 tiles(BN=128) x 9 chunks
            int kb = chunk * 96 / 9, ke = (chunk + 1) * 96 / 9;
            gemm2<128, 8, 2>(g_X, Emb, P.W_ih0, Emb, 32,
                             g_H0, Hid, P.W_hh0, Hid,
                             kb, ke, tile * 128,
                             g_part + (size_t)chunk * Bsz * G4, G4, sA, sW);
        }
        grid_sync(lgen);
        gate_phase(g_bias0, g_H0, g_C0, gtid);
        grid_sync(lgen);

        // ---- layer 1: g = H0 @ W_ih1^T + H1 @ W_hh1^T (virtual K = 1024|1024, 128 k-tiles)
        {
            int tile = blk % 32, chunk = blk / 32;
            int kb = chunk * 128 / 9, ke = (chunk + 1) * 128 / 9;
            gemm2<128, 8, 2>(g_H0, Hid, P.W_ih1, Hid, 64,
                             g_H1, Hid, P.W_hh1, Hid,
                             kb, ke, tile * 128,
                             g_part + (size_t)chunk * Bsz * G4, G4, sA, sW);
        }
        grid_sync(lgen);
        gate_phase(g_bias1, g_H1, g_C1, gtid);
        grid_sync(lgen);

        // ---- logits: H1 @ fc_w^T (K = 1024 = 64 k-tiles; 16 tiles(BN=32) x 18 chunks)
        {
            int tile = blk % 16, chunk = blk / 16;
            int kb = chunk * 64 / 18, ke = (chunk + 1) * 64 / 18;
            gemm2<32, 4, 1>(g_H1, Hid, P.fc_w, Hid, 64,
                            g_H1, Hid, P.fc_w, Hid,   // seg1 never reached
                            kb, ke, tile * 32,
                            g_lpart + (size_t)chunk * Bsz * Vocab, Vocab, sA, sW);
        }
        grid_sync(lgen);

        // ---- epilogue: sum 18 partials + bias, write out, argmax, next-token embed
        if (blk < 128) {
            int b = blk;
            float* orow = P.out + ((size_t)b * Tlen + t) * Vocab;
            float bv = -3.402823e38f; int bi = 0;
            for (int n = tid; n < Vocab; n += NTHR) {
                float v = P.fc_b[n];
#pragma unroll
                for (int ch = 0; ch < 18; ch++)
                    v += g_lpart[(size_t)ch * Bsz * Vocab + b * Vocab + n];
                orow[n] = v;
                if (v > bv) { bv = v; bi = n; }
            }
            red_v[tid] = bv; red_i[tid] = bi;
            __syncthreads();
            for (int s = NTHR / 2; s > 0; s >>= 1) {
                if (tid < s) {
                    float v2 = red_v[tid + s]; int i2 = red_i[tid + s];
                    if (v2 > red_v[tid] || (v2 == red_v[tid] && i2 < red_i[tid])) {
                        red_v[tid] = v2; red_i[tid] = i2;
                    }
                }
                __syncthreads();
            }
            if (t + 1 < Tlen) {
                if (tid == 0) {
                    bool teacher = g_dec[(t + 1) * Bsz + b] != 0;
                    s_tok = teacher ? P.seq[b * Tlen + (t + 1)] : red_i[0];
                }
                __syncthreads();
                int tok = s_tok;
                const float4* src = (const float4*)(P.embeds + (size_t)tok * Emb);
                float4* dst = (float4*)(g_X + (size_t)b * Emb);
                if (tid < 128)
                    dst[tid] = (tok == 0) ? make_float4(0.f, 0.f, 0.f, 0.f) : src[tid];
            }
        }
        grid_sync(lgen);
    }
}

// ---------------- host launch: ONE kernel node, fully graph-capturable ----------------
extern "C" void kernel_launch(void* const* d_in, const int* in_sizes, int n_in,
                              void* d_out, int out_size)
{
    Params P;
    P.seq       = (const int*)d_in[0];
    // d_in[1] = seq_lens (unused by the reference computation)
    P.teacher_p = (const float*)d_in[2];
    P.embeds    = (const float*)d_in[3];
    P.W_ih0     = (const float*)d_in[4];
    P.W_hh0     = (const float*)d_in[5];
    P.b_ih0     = (const float*)d_in[6];
    P.b_hh0     = (const float*)d_in[7];
    P.W_ih1     = (const float*)d_in[8];
    P.W_hh1     = (const float*)d_in[9];
    P.b_ih1     = (const float*)d_in[10];
    P.b_hh1     = (const float*)d_in[11];
    P.fc_w      = (const float*)d_in[12];
    P.fc_b      = (const float*)d_in[13];
    P.out       = (float*)d_out;

    lstm_persist<<<GRIDB, NTHR>>>(P);
}